// round 2
// baseline (speedup 1.0000x reference)
#include <cuda_runtime.h>
#include <cstdint>

#define B_IMG 16
#define HGT 1024
#define WID 1024
#define HW (1u << 20)
#define CAP (1 << 17)          // per-image candidate capacity (NMS floor-spacing bound ~16.6K)
#define NEG_INF __int_as_float(0xff800000)

// ---------------- scratch (device globals; no allocations allowed) ----------------
__device__ float g_R[(size_t)B_IMG * HW];        // Shi-Tomasi response
__device__ int   g_RmaxBits[B_IMG];              // per-image max(R) as int bits
__device__ int   g_count[B_IMG];                 // per-image candidate count
__device__ unsigned int g_candIdx[B_IMG][CAP];
__device__ float        g_candVal[B_IMG][CAP];

// ---------------- init ----------------
__global__ void initK() {
    int t = threadIdx.x;
    if (t < B_IMG) { g_RmaxBits[t] = 0; g_count[t] = 0; }
}

// ---------------- fused response kernel ----------------
// 32x32 output tile. Image halo of 4 (1 sobel + 3 box).
// Gradient products outside the image are 0 (reference box-filters HxW arrays
// with zero SAME padding); sobel at border pixels uses the zero-padded image.
__global__ void __launch_bounds__(256) computeR(const float* __restrict__ img) {
    const int b  = blockIdx.z;
    const int X0 = blockIdx.x * 32;
    const int Y0 = blockIdx.y * 32;

    __shared__ float S[40][41];
    __shared__ float Pxx[38][39], Pyy[38][39], Pxy[38][39];
    __shared__ float Hxx[38][33], Hyy[38][33], Hxy[38][33];
    __shared__ float warpMax[8];

    const float* im = img + (size_t)b * HW;
    const int tid = threadIdx.y * 32 + threadIdx.x;

    // 1) load + quantize image tile with 4-halo; zero pad outside
    for (int i = tid; i < 40 * 40; i += 256) {
        int r = i / 40, c = i % 40;
        int gy = Y0 - 4 + r, gx = X0 - 4 + c;
        float v = 0.0f;
        if (gy >= 0 && gy < HGT && gx >= 0 && gx < WID) {
            float t = im[gy * WID + gx];
            v = fminf(fmaxf(floorf(t * 255.0f), 0.0f), 255.0f) / 255.0f;
        }
        S[r][c] = v;
    }
    __syncthreads();

    // 2) sobel gradients + products on 38x38 region (global rows Y0-3 .. Y0+34)
    for (int i = tid; i < 38 * 38; i += 256) {
        int r = i / 38, c = i % 38;
        int gy = Y0 - 3 + r, gx = X0 - 3 + c;
        float pxx = 0.0f, pyy = 0.0f, pxy = 0.0f;
        if (gy >= 0 && gy < HGT && gx >= 0 && gx < WID) {
            float ix = (S[r][c + 2] - S[r][c])
                     + 2.0f * (S[r + 1][c + 2] - S[r + 1][c])
                     + (S[r + 2][c + 2] - S[r + 2][c]);
            float iy = (S[r + 2][c] + 2.0f * S[r + 2][c + 1] + S[r + 2][c + 2])
                     - (S[r][c] + 2.0f * S[r][c + 1] + S[r][c + 2]);
            pxx = ix * ix; pyy = iy * iy; pxy = ix * iy;
        }
        Pxx[r][c] = pxx; Pyy[r][c] = pyy; Pxy[r][c] = pxy;
    }
    __syncthreads();

    // 3) horizontal 7-sum -> 38x32
    for (int i = tid; i < 38 * 32; i += 256) {
        int r = i / 32, c = i % 32;
        float a = 0.0f, d = 0.0f, e = 0.0f;
#pragma unroll
        for (int k = 0; k < 7; k++) { a += Pxx[r][c + k]; d += Pyy[r][c + k]; e += Pxy[r][c + k]; }
        Hxx[r][c] = a; Hyy[r][c] = d; Hxy[r][c] = e;
    }
    __syncthreads();

    // 4) vertical 7-sum + response
    float localMax = 0.0f;
    for (int i = tid; i < 32 * 32; i += 256) {
        int ly = i / 32, lx = i % 32;
        float sxx = 0.0f, syy = 0.0f, sxy = 0.0f;
#pragma unroll
        for (int k = 0; k < 7; k++) { sxx += Hxx[ly + k][lx]; syy += Hyy[ly + k][lx]; sxy += Hxy[ly + k][lx]; }
        float ht = 0.5f * (sxx + syy);
        float dd = 0.5f * (sxx - syy);
        float r  = ht - sqrtf(dd * dd + sxy * sxy);
        g_R[((size_t)b << 20) + (size_t)(Y0 + ly) * WID + (X0 + lx)] = r;
        localMax = fmaxf(localMax, r);
    }

#pragma unroll
    for (int o = 16; o > 0; o >>= 1)
        localMax = fmaxf(localMax, __shfl_xor_sync(0xffffffffu, localMax, o));
    if ((tid & 31) == 0) warpMax[tid >> 5] = localMax;
    __syncthreads();
    if (tid == 0) {
        float m = warpMax[0];
#pragma unroll
        for (int i = 1; i < 8; i++) m = fmaxf(m, warpMax[i]);
        atomicMax(&g_RmaxBits[b], __float_as_int(m));
    }
}

// ---------------- fused 15x15 NMS + threshold + candidate collect ----------------
// 32x32 output tile; loads 46x46 R halo tile, separable 15-max in smem.
__global__ void __launch_bounds__(256) nmsCollect() {
    const int b  = blockIdx.z;
    const int X0 = blockIdx.x * 32;
    const int Y0 = blockIdx.y * 32;

    __shared__ float sh[46][48];     // 46x46 R tile (+pad)
    __shared__ float hm[46][32];     // horizontal 15-max
    __shared__ float shThr;
    const int tid = threadIdx.y * 32 + threadIdx.x;
    const float* Rb = g_R + ((size_t)b << 20);

    // load 46x46 halo tile, -inf outside (matches reduce_window init -inf)
    for (int i = tid; i < 46 * 46; i += 256) {
        int r = i / 46, c = i % 46;
        int gy = Y0 - 7 + r, gx = X0 - 7 + c;
        sh[r][c] = (gy >= 0 && gy < HGT && gx >= 0 && gx < WID)
                   ? Rb[(size_t)gy * WID + gx] : NEG_INF;
    }
    if (tid == 0) shThr = 0.3f * __int_as_float(g_RmaxBits[b]);
    __syncthreads();

    // horizontal 15-max: 46 rows x 32 cols
    for (int i = tid; i < 46 * 32; i += 256) {
        int r = i / 32, c = i % 32;
        float m = sh[r][c];
#pragma unroll
        for (int d = 1; d < 15; d++) m = fmaxf(m, sh[r][c + d]);
        hm[r][c] = m;
    }
    __syncthreads();

    const float thr = shThr;
    const int lx = threadIdx.x;
#pragma unroll
    for (int s = 0; s < 4; s++) {
        int ly = threadIdx.y + 8 * s;
        float pooled = hm[ly][lx];
#pragma unroll
        for (int d = 1; d < 15; d++) pooled = fmaxf(pooled, hm[ly + d][lx]);
        float r = sh[ly + 7][lx + 7];          // center R, reused from smem
        if (r >= pooled && r >= thr) {
            int y = Y0 + ly, x = X0 + lx;
            int pos = atomicAdd(&g_count[b], 1);
            if (pos < CAP) {
                g_candIdx[b][pos] = (unsigned int)(y * WID + x);
                g_candVal[b][pos] = r;
            }
        }
    }
}

// ---------------- exact per-image top-K (MSD radix select on 64-bit key) ----------------
// key = (valueBits << 32) | (~idx)  -> desc key order == value desc, idx asc (JAX tie-break)
__global__ void __launch_bounds__(256) selectK(float* __restrict__ out, const int* __restrict__ topkPtr) {
    const int b   = blockIdx.x;
    const int tid = threadIdx.x;
    const int topK = *topkPtr;
    int n = g_count[b]; if (n > CAP) n = CAP;

    __shared__ unsigned long long shK;
    __shared__ int shRem;
    __shared__ int hist[256];

    if (tid == 0) { shK = 0ull; shRem = topK; }
    __syncthreads();

    if (n > topK) {
        for (int byte = 7; byte >= 0; byte--) {
            for (int i = tid; i < 256; i += 256) hist[i] = 0;
            __syncthreads();
            const unsigned long long pref = shK;
            const int shift = byte * 8;
            for (int i = tid; i < n; i += 256) {
                unsigned int vb = __float_as_uint(g_candVal[b][i]);
                unsigned long long key =
                    ((unsigned long long)vb << 32) | (unsigned long long)(0xFFFFFFFFu - g_candIdx[b][i]);
                bool match = (byte == 7) || ((key >> (shift + 8)) == (pref >> (shift + 8)));
                if (match) atomicAdd(&hist[(int)((key >> shift) & 255)], 1);
            }
            __syncthreads();
            if (tid == 0) {
                int rem = shRem, cum = 0, chosen = 0;
                for (int bin = 255; bin >= 0; bin--) {
                    int c = hist[bin];
                    if (cum + c >= rem) { chosen = bin; shRem = rem - cum; break; }
                    cum += c;
                }
                shK = pref | ((unsigned long long)chosen << shift);
            }
            __syncthreads();
        }
    }
    const unsigned long long K = (n > topK) ? shK : 0ull;
    for (int i = tid; i < n; i += 256) {
        unsigned int vb  = __float_as_uint(g_candVal[b][i]);
        unsigned int idx = g_candIdx[b][i];
        unsigned long long key = ((unsigned long long)vb << 32) | (unsigned long long)(0xFFFFFFFFu - idx);
        if (key >= K) out[((size_t)b << 20) + idx] = 1.0f;
    }
}

// ---------------- launch ----------------
extern "C" void kernel_launch(void* const* d_in, const int* in_sizes, int n_in,
                              void* d_out, int out_size) {
    const float* img  = (const float*)d_in[0];
    const int*   topk = (const int*)d_in[1];
    float*       out  = (float*)d_out;

    cudaMemsetAsync(d_out, 0, (size_t)out_size * sizeof(float), 0);
    initK<<<1, 32>>>();
    computeR<<<dim3(32, 32, B_IMG), dim3(32, 8)>>>(img);
    nmsCollect<<<dim3(32, 32, B_IMG), dim3(32, 8)>>>();
    selectK<<<B_IMG, 256>>>(out, topk);
}

// round 4
// speedup vs baseline: 1.2048x; 1.2048x over previous
#include <cuda_runtime.h>
#include <cstdint>

#define B_IMG 16
#define HGT 1024
#define WID 1024
#define HW (1u << 20)
#define CAP (1 << 17)
#define NEG_INF __int_as_float(0xff800000)

// ---------------- scratch ----------------
__device__ float g_R[(size_t)B_IMG * HW];
__device__ int   g_RmaxBits[B_IMG];
__device__ int   g_count[B_IMG];
__device__ unsigned long long g_candKey[B_IMG][CAP];  // (valBits<<32)|(~idx)

__global__ void initK() {
    int t = threadIdx.x;
    if (t < B_IMG) { g_RmaxBits[t] = 0; g_count[t] = 0; }
}

__device__ __forceinline__ float4 ld4(const float* p) { return *(const float4*)p; }
__device__ __forceinline__ void st4(float* p, float4 v) { *(float4*)p = v; }

// 7-tap horizontal box sum for 4 adjacent outputs from 12 consecutive values
__device__ __forceinline__ float4 hsum7(float4 A, float4 B, float4 C) {
    float common = (A.w + B.x) + (B.y + B.z);      // v3+v4+v5+v6
    float4 r;
    r.x = ((A.x + A.y) + A.z) + common;            // v0..v6
    r.y = (A.y + A.z) + common + B.w;              // v1..v7
    r.z = A.z + common + (B.w + C.x);              // v2..v8
    r.w = common + ((B.w + C.x) + C.y);            // v3..v9
    return r;
}

// 15-tap horizontal max for 4 adjacent outputs from 18 consecutive values
// common covers v3..v14 (FIXED: includes B.w = v7)
__device__ __forceinline__ float4 hmax15(float4 A, float4 B, float4 C, float4 D, float4 E) {
    float common = fmaxf(fmaxf(fmaxf(fmaxf(A.w, B.x), fmaxf(B.y, B.z)), B.w),
                   fmaxf(fmaxf(fmaxf(C.x, C.y), fmaxf(C.z, C.w)),
                         fmaxf(D.x, fmaxf(D.y, D.z))));            // v3..v14
    float4 r;
    r.x = fmaxf(common, fmaxf(fmaxf(A.x, A.y), A.z));              // v0..v14
    r.y = fmaxf(common, fmaxf(fmaxf(A.y, A.z), D.w));              // v1..v15
    r.z = fmaxf(common, fmaxf(fmaxf(A.z, D.w), E.x));              // v2..v16
    r.w = fmaxf(common, fmaxf(fmaxf(D.w, E.x), E.y));              // v3..v17
    return r;
}

// ---------------- fused response kernel (32x32 tile, float4 phases) ----------------
__global__ void __launch_bounds__(256) computeR(const float* __restrict__ img) {
    const int b  = blockIdx.z;
    const int X0 = blockIdx.x * 32;
    const int Y0 = blockIdx.y * 32;

    __shared__ __align__(16) float S[40][44];                 // gy=Y0-4+r, gx=X0-4+c
    __shared__ __align__(16) float Pxx[38][40], Pyy[38][40], Pxy[38][40];  // gy=Y0-3+r, gx=X0-3+c
    __shared__ __align__(16) float Hxx[38][32], Hyy[38][32], Hxy[38][32];
    __shared__ float warpMax[8];

    const float* im = img + (size_t)b * HW;
    const int tid = threadIdx.x;

    // phase 1: load + quantize image with 4-halo; zero outside; pad cols 40-43 = 0
    for (int i = tid; i < 40 * 44; i += 256) {
        int r = i / 44, c = i % 44;
        int gy = Y0 - 4 + r, gx = X0 - 4 + c;
        float v = 0.0f;
        if (c < 40 && gy >= 0 && gy < HGT && gx >= 0 && gx < WID) {
            float t = im[gy * WID + gx];
            v = fminf(fmaxf(floorf(t * 255.0f), 0.0f), 255.0f) / 255.0f;
        }
        S[r][c] = v;
    }
    __syncthreads();

    // phase 2: sobel products, 4 cols/thread. tasks = 38 rows x 10 chunks
    for (int i = tid; i < 380; i += 256) {
        int r = i / 10, c0 = (i - r * 10) * 4;
        int gy = Y0 - 3 + r;
        float4 a0 = ld4(&S[r][c0]),     a1 = ld4(&S[r][c0 + 4]);
        float4 b0 = ld4(&S[r + 1][c0]), b1 = ld4(&S[r + 1][c0 + 4]);
        float4 d0 = ld4(&S[r + 2][c0]), d1 = ld4(&S[r + 2][c0 + 4]);
        float s0[6] = {a0.x, a0.y, a0.z, a0.w, a1.x, a1.y};
        float s1[6] = {b0.x, b0.y, b0.z, b0.w, b1.x, b1.y};
        float s2[6] = {d0.x, d0.y, d0.z, d0.w, d1.x, d1.y};
        float rowOK = (gy >= 0 && gy < HGT) ? 1.0f : 0.0f;
        float oxx[4], oyy[4], oxy[4];
#pragma unroll
        for (int j = 0; j < 4; j++) {
            int gx = X0 - 3 + c0 + j;
            float m = (gx >= 0 && gx < WID) ? rowOK : 0.0f;
            float ix = (s0[j + 2] - s0[j])
                     + 2.0f * (s1[j + 2] - s1[j])
                     + (s2[j + 2] - s2[j]);
            float iy = (s2[j] + 2.0f * s2[j + 1] + s2[j + 2])
                     - (s0[j] + 2.0f * s0[j + 1] + s0[j + 2]);
            oxx[j] = ix * ix * m; oyy[j] = iy * iy * m; oxy[j] = ix * iy * m;
        }
        st4(&Pxx[r][c0], make_float4(oxx[0], oxx[1], oxx[2], oxx[3]));
        st4(&Pyy[r][c0], make_float4(oyy[0], oyy[1], oyy[2], oyy[3]));
        st4(&Pxy[r][c0], make_float4(oxy[0], oxy[1], oxy[2], oxy[3]));
    }
    __syncthreads();

    // phase 3: horizontal 7-sum, 4 cols/thread. tasks = 38 rows x 8 chunks
    for (int i = tid; i < 304; i += 256) {
        int r = i >> 3, c0 = (i & 7) << 2;
        st4(&Hxx[r][c0], hsum7(ld4(&Pxx[r][c0]), ld4(&Pxx[r][c0 + 4]), ld4(&Pxx[r][c0 + 8])));
        st4(&Hyy[r][c0], hsum7(ld4(&Pyy[r][c0]), ld4(&Pyy[r][c0 + 4]), ld4(&Pyy[r][c0 + 8])));
        st4(&Hxy[r][c0], hsum7(ld4(&Pxy[r][c0]), ld4(&Pxy[r][c0 + 4]), ld4(&Pxy[r][c0 + 8])));
    }
    __syncthreads();

    // phase 4: vertical 7-sum + response (1 task/thread: 32 rows x 8 chunks)
    float localMax = 0.0f;
    {
        int r = tid >> 3, c0 = (tid & 7) << 2;
        float4 sxx = ld4(&Hxx[r][c0]);
        float4 syy = ld4(&Hyy[r][c0]);
        float4 sxy = ld4(&Hxy[r][c0]);
#pragma unroll
        for (int k = 1; k < 7; k++) {
            float4 t;
            t = ld4(&Hxx[r + k][c0]); sxx.x += t.x; sxx.y += t.y; sxx.z += t.z; sxx.w += t.w;
            t = ld4(&Hyy[r + k][c0]); syy.x += t.x; syy.y += t.y; syy.z += t.z; syy.w += t.w;
            t = ld4(&Hxy[r + k][c0]); sxy.x += t.x; sxy.y += t.y; sxy.z += t.z; sxy.w += t.w;
        }
        float4 R;
        {
            float ht = 0.5f * (sxx.x + syy.x), dd = 0.5f * (sxx.x - syy.x);
            R.x = ht - sqrtf(dd * dd + sxy.x * sxy.x);
            ht = 0.5f * (sxx.y + syy.y); dd = 0.5f * (sxx.y - syy.y);
            R.y = ht - sqrtf(dd * dd + sxy.y * sxy.y);
            ht = 0.5f * (sxx.z + syy.z); dd = 0.5f * (sxx.z - syy.z);
            R.z = ht - sqrtf(dd * dd + sxy.z * sxy.z);
            ht = 0.5f * (sxx.w + syy.w); dd = 0.5f * (sxx.w - syy.w);
            R.w = ht - sqrtf(dd * dd + sxy.w * sxy.w);
        }
        *(float4*)&g_R[((size_t)b << 20) + (size_t)(Y0 + r) * WID + (X0 + c0)] = R;
        localMax = fmaxf(fmaxf(R.x, R.y), fmaxf(R.z, R.w));
    }

#pragma unroll
    for (int o = 16; o > 0; o >>= 1)
        localMax = fmaxf(localMax, __shfl_xor_sync(0xffffffffu, localMax, o));
    if ((tid & 31) == 0) warpMax[tid >> 5] = localMax;
    __syncthreads();
    if (tid == 0) {
        float m = warpMax[0];
#pragma unroll
        for (int i = 1; i < 8; i++) m = fmaxf(m, warpMax[i]);
        atomicMax(&g_RmaxBits[b], __float_as_int(m));
    }
}

// ---------------- fused 15x15 NMS + threshold + collect (float4) ----------------
__global__ void __launch_bounds__(256) nmsCollect() {
    const int b  = blockIdx.z;
    const int X0 = blockIdx.x * 32;
    const int Y0 = blockIdx.y * 32;

    __shared__ __align__(16) float sh[46][48];   // gy=Y0-7+r, gx=X0-7+c; cols 46-47 pad -inf
    __shared__ __align__(16) float hm[46][32];
    __shared__ float shThr;
    const int tid = threadIdx.x;
    const float* Rb = g_R + ((size_t)b << 20);

    for (int i = tid; i < 46 * 48; i += 256) {
        int r = i / 48, c = i % 48;
        int gy = Y0 - 7 + r, gx = X0 - 7 + c;
        sh[r][c] = (c < 46 && gy >= 0 && gy < HGT && gx >= 0 && gx < WID)
                   ? Rb[(size_t)gy * WID + gx] : NEG_INF;
    }
    if (tid == 0) shThr = 0.3f * __int_as_float(g_RmaxBits[b]);
    __syncthreads();

    // horizontal 15-max: tasks = 46 rows x 8 chunks
    for (int i = tid; i < 368; i += 256) {
        int r = i >> 3, c0 = (i & 7) << 2;
        st4(&hm[r][c0], hmax15(ld4(&sh[r][c0]),      ld4(&sh[r][c0 + 4]),
                               ld4(&sh[r][c0 + 8]),  ld4(&sh[r][c0 + 12]),
                               ld4(&sh[r][c0 + 16])));
    }
    __syncthreads();

    // vertical 15-max + threshold + append (1 task/thread)
    const float thr = shThr;
    {
        int r = tid >> 3, c0 = (tid & 7) << 2;
        float4 pooled = ld4(&hm[r][c0]);
#pragma unroll
        for (int k = 1; k < 15; k++) {
            float4 t = ld4(&hm[r + k][c0]);
            pooled.x = fmaxf(pooled.x, t.x); pooled.y = fmaxf(pooled.y, t.y);
            pooled.z = fmaxf(pooled.z, t.z); pooled.w = fmaxf(pooled.w, t.w);
        }
        float cen[4] = { sh[r + 7][c0 + 7], sh[r + 7][c0 + 8],
                         sh[r + 7][c0 + 9], sh[r + 7][c0 + 10] };
        float pool[4] = { pooled.x, pooled.y, pooled.z, pooled.w };
#pragma unroll
        for (int j = 0; j < 4; j++) {
            float rv = cen[j];
            if (rv >= pool[j] && rv >= thr) {
                unsigned int idx = (unsigned int)((Y0 + r) * WID + (X0 + c0 + j));
                int pos = atomicAdd(&g_count[b], 1);
                if (pos < CAP)
                    g_candKey[b][pos] = ((unsigned long long)__float_as_uint(rv) << 32)
                                      | (unsigned long long)(0xFFFFFFFFu - idx);
            }
        }
    }
}

// ---------------- exact per-image top-K: MSD radix select, parallel scan, early exit ----------------
__global__ void __launch_bounds__(512) selectK(float* __restrict__ out, const int* __restrict__ topkPtr) {
    const int b   = blockIdx.x;
    const int tid = threadIdx.x;
    const int topK = *topkPtr;
    int n = g_count[b]; if (n > CAP) n = CAP;

    __shared__ int hist[256];
    __shared__ int suf[256];
    __shared__ unsigned long long shK;
    __shared__ int shRem, shDone;

    if (tid == 0) { shK = 0ull; shRem = topK; shDone = (n <= topK) ? 1 : 0; }
    __syncthreads();

    for (int byte = 7; byte >= 0; byte--) {
        if (shDone) break;
        if (tid < 256) hist[tid] = 0;
        __syncthreads();
        const unsigned long long pref = shK;
        const int shift = byte * 8;
        for (int i = tid; i < n; i += 512) {
            unsigned long long key = g_candKey[b][i];
            bool match = (byte == 7) || ((key >> (shift + 8)) == (pref >> (shift + 8)));
            if (match) atomicAdd(&hist[(int)((key >> shift) & 255)], 1);
        }
        __syncthreads();
        if (tid < 256) suf[tid] = hist[tid];
        __syncthreads();
        // inclusive suffix sum over 256 bins
        for (int off = 1; off < 256; off <<= 1) {
            int v = 0;
            if (tid < 256 && tid + off < 256) v = suf[tid + off];
            __syncthreads();
            if (tid < 256) suf[tid] += v;
            __syncthreads();
        }
        if (tid < 256) {
            int rem   = shRem;
            int here  = suf[tid];
            int above = (tid < 255) ? suf[tid + 1] : 0;
            if (here >= rem && above < rem) {        // unique boundary bin
                int inBin = rem - above;
                int cnt   = here - above;
                unsigned long long newK = pref | ((unsigned long long)(unsigned int)tid << shift);
                shK = newK;
                if (inBin == cnt || byte == 0) shDone = 1;
                else shRem = inBin;
            }
        }
        __syncthreads();
    }

    const unsigned long long K = (n <= topK) ? 0ull : shK;
    for (int i = tid; i < n; i += 512) {
        unsigned long long key = g_candKey[b][i];
        if (key >= K) {
            unsigned int idx = 0xFFFFFFFFu - (unsigned int)(key & 0xFFFFFFFFull);
            out[((size_t)b << 20) + idx] = 1.0f;
        }
    }
}

// ---------------- launch ----------------
extern "C" void kernel_launch(void* const* d_in, const int* in_sizes, int n_in,
                              void* d_out, int out_size) {
    const float* img  = (const float*)d_in[0];
    const int*   topk = (const int*)d_in[1];
    float*       out  = (float*)d_out;

    cudaMemsetAsync(d_out, 0, (size_t)out_size * sizeof(float), 0);
    initK<<<1, 32>>>();
    computeR<<<dim3(32, 32, B_IMG), 256>>>(img);
    nmsCollect<<<dim3(32, 32, B_IMG), 256>>>();
    selectK<<<B_IMG, 512>>>(out, topk);
}